// round 14
// baseline (speedup 1.0000x reference)
#include <cuda_runtime.h>
#include <cstdint>
#include <math.h>

#define N_NODES 50000
#define N_EDGES 640000
#define NH (N_NODES * 128)
#define NB 196  // ceil(N_NODES / 256)

// ---------------- scratch (static device globals) ---------------------------
// INVARIANT: g_indeg and g_cursor are zero at the start of every kernel_launch
// call: zero-initialized at module load; scan_bc re-zeros g_indeg after
// consuming it and zeroes g_cursor before fill uses it, every run.
__device__ uint32_t g_hhb[NH / 2];    // Hs @ gcn_w (unscaled), bf16x2 packed
// f16x2 weights as LDS.128 fragment image, per matrix (i,c,o,gcn):
// i = m*8192 + c*4096 + ks*1024 + nw*128 + q*16 + r*4 + s*2 + hi
// where k2 = c*32 + ks*8 + hi*4 + r ; n = nw*16 + s*8 + q
// u32 = {W[2k2][n] lo, W[2k2+1][n] hi}
__device__ uint32_t g_Wc[4 * 8192];
__device__ int   g_indeg[N_NODES];
__device__ float g_dg[N_NODES];       // rsqrt(1 + indeg)
__device__ int   g_off[N_NODES + 1];
__device__ int   g_cursor[N_NODES];
__device__ int   g_csr[N_EDGES];
__device__ int   g_part[256];
// fused per-channel constants
__device__ float g_cb0[128], g_cb1[128], g_cb2[128], g_wc2[128];
__device__ float g_fa[128];
__device__ float g_fc;

// ---------------- helpers ----------------------------------------------------
__device__ __forceinline__ float tanhfast(float x) {
    float r; asm("tanh.approx.f32 %0, %1;" : "=f"(r) : "f"(x)); return r;
}
__device__ __forceinline__ float sigfast(float x) {
    return 0.5f * tanhfast(0.5f * x) + 0.5f;
}
__device__ __forceinline__ uint32_t pack_bf16x2(float hi, float lo) {
    uint32_t u; asm("cvt.rn.bf16x2.f32 %0, %1, %2;" : "=r"(u) : "f"(hi), "f"(lo)); return u;
}
__device__ __forceinline__ uint32_t pack_f16x2(float hi, float lo) {
    uint32_t u; asm("cvt.rn.f16x2.f32 %0, %1, %2;" : "=r"(u) : "f"(hi), "f"(lo)); return u;
}
__device__ __forceinline__ float bf_lo(uint32_t u) { return __uint_as_float(u << 16); }
__device__ __forceinline__ float bf_hi(uint32_t u) { return __uint_as_float(u & 0xffff0000u); }
__device__ __forceinline__ void mma_f16(float* d, uint32_t a0, uint32_t a1,
                                        uint32_t a2, uint32_t a3,
                                        uint32_t b0, uint32_t b1) {
    asm volatile(
        "mma.sync.aligned.m16n8k16.row.col.f32.f16.f16.f32 "
        "{%0,%1,%2,%3}, {%4,%5,%6,%7}, {%8,%9}, {%0,%1,%2,%3};"
        : "+f"(d[0]), "+f"(d[1]), "+f"(d[2]), "+f"(d[3])
        : "r"(a0), "r"(a1), "r"(a2), "r"(a3), "r"(b0), "r"(b1));
}
__device__ __forceinline__ uint32_t smem_u32(const void* p) {
    uint32_t a;
    asm("{ .reg .u64 t; cvta.to.shared.u64 t, %1; cvt.u32.u64 %0, t; }" : "=r"(a) : "l"(p));
    return a;
}
__device__ __forceinline__ void cp_async16(uint32_t daddr, const void* saddr, int srcsz) {
    asm volatile("cp.async.cg.shared.global [%0], [%1], 16, %2;"
                 :: "r"(daddr), "l"(saddr), "r"(srcsz) : "memory");
}

// ---------------- prep: weights -> LDS.128 fragment image + constants --------
__global__ void prep_all(const float* __restrict__ Wx, const float* __restrict__ gcn,
                         const float* __restrict__ theta_b, const float* __restrict__ b,
                         const float* __restrict__ w_c,
                         const float* __restrict__ gamma, const float* __restrict__ beta,
                         const float* __restrict__ mean, const float* __restrict__ var,
                         const float* __restrict__ lin_w, const float* __restrict__ lin_b) {
    if (blockIdx.x < 128) {
        int i = blockIdx.x * 256 + threadIdx.x;   // 0..32767
        int m  = i >> 13;
        int c  = (i >> 12) & 1;
        int ks = (i >> 10) & 3;
        int nw = (i >> 7) & 7;
        int q  = (i >> 4) & 7;
        int r  = (i >> 2) & 3;
        int s  = (i >> 1) & 1;
        int hi = i & 1;
        int k2 = c * 32 + ks * 8 + hi * 4 + r;
        int n  = nw * 16 + s * 8 + q;
        const float* S = (m == 0) ? Wx
                       : (m == 1) ? Wx + 2 * 16384
                       : (m == 2) ? Wx + 3 * 16384 : gcn;
        g_Wc[i] = pack_f16x2(S[(2 * k2 + 1) * 128 + n], S[2 * k2 * 128 + n]);
        return;
    }
    int ch = threadIdx.x;
    if (ch >= 128) return;
    g_cb0[ch] = theta_b[ch] + b[ch];
    g_cb1[ch] = theta_b[256 + ch] + b[256 + ch];
    g_cb2[ch] = theta_b[384 + ch] + b[384 + ch];
    g_wc2[ch] = w_c[256 + ch];
    float sc = gamma[ch] * rsqrtf(var[ch] + 1e-5f);
    g_fa[ch] = sc * lin_w[ch];
    __shared__ float red[128];
    red[ch] = (beta[ch] - mean[ch] * sc) * lin_w[ch];
    __syncthreads();
    for (int o = 64; o > 0; o >>= 1) { if (ch < o) red[ch] += red[ch + o]; __syncthreads(); }
    if (ch == 0) g_fc = red[0] + lin_b[0];
}

__global__ void count_kernel(const int* __restrict__ dst) {
    int e = blockIdx.x * blockDim.x + threadIdx.x;
    if (e < N_EDGES) atomicAdd(&g_indeg[dst[e]], 1);
}

// ---- scan stage A ----
__global__ __launch_bounds__(256) void scan_a() {
    int i = blockIdx.x * 256 + threadIdx.x;
    int v = (i < N_NODES) ? g_indeg[i] : 0;
    int lane = threadIdx.x & 31, warp = threadIdx.x >> 5;
#pragma unroll
    for (int o = 16; o > 0; o >>= 1) v += __shfl_down_sync(0xffffffffu, v, o);
    __shared__ int ws[8];
    if (lane == 0) ws[warp] = v;
    __syncthreads();
    if (threadIdx.x == 0) {
        int s = 0;
#pragma unroll
        for (int w = 0; w < 8; w++) s += ws[w];
        g_part[blockIdx.x] = s;
    }
}
// ---- scan stage BC ----
__global__ __launch_bounds__(256) void scan_bc() {
    int t = threadIdx.x, lane = t & 31, warp = t >> 5;
    __shared__ int s2[256];
    __shared__ int ws[8];
    {
        int v = (t < NB) ? g_part[t] : 0;
        int x = v;
#pragma unroll
        for (int o = 1; o < 32; o <<= 1) {
            int y = __shfl_up_sync(0xffffffffu, x, o);
            if (lane >= o) x += y;
        }
        if (lane == 31) ws[warp] = x;
        __syncthreads();
        if (warp == 0 && lane < 8) {
            int w = ws[lane];
#pragma unroll
            for (int o = 1; o < 8; o <<= 1) {
                int y = __shfl_up_sync(0xffu, w, o);
                if (lane >= o) w += y;
            }
            ws[lane] = w;
        }
        __syncthreads();
        s2[t] = x + (warp > 0 ? ws[warp - 1] : 0);
        __syncthreads();
    }
    int blockbase = (blockIdx.x == 0) ? 0 : s2[blockIdx.x - 1];
    __syncthreads();
    int i = blockIdx.x * 256 + t;
    int v = (i < N_NODES) ? g_indeg[i] : 0;
    int x = v;
#pragma unroll
    for (int o = 1; o < 32; o <<= 1) {
        int y = __shfl_up_sync(0xffffffffu, x, o);
        if (lane >= o) x += y;
    }
    if (lane == 31) ws[warp] = x;
    __syncthreads();
    if (warp == 0 && lane < 8) {
        int w = ws[lane];
#pragma unroll
        for (int o = 1; o < 8; o <<= 1) {
            int y = __shfl_up_sync(0xffu, w, o);
            if (lane >= o) w += y;
        }
        ws[lane] = w;
    }
    __syncthreads();
    if (i < N_NODES) {
        g_off[i] = x - v + (warp > 0 ? ws[warp - 1] : 0) + blockbase;
        g_dg[i] = rsqrtf(1.0f + (float)v);
        g_cursor[i] = 0;
        g_indeg[i] = 0;  // restore invariant for next replay
    }
    if (blockIdx.x == 0 && t == 0) g_off[N_NODES] = N_EDGES;
}

__global__ void fill_kernel(const int* __restrict__ src, const int* __restrict__ dst) {
    int e = blockIdx.x * blockDim.x + threadIdx.x;
    if (e >= N_EDGES) return;
    int d = dst[e];
    g_csr[g_off[d] + atomicAdd(&g_cursor[d], 1)] = src[e];
}

// ============================================================================
// Fused f16-MMA GEMM, 256 threads, M-tile 64, 8 warps (2m x 4n), tile 32x32.
// 2 CTAs/SM. LDS.128 fragment packing: A frag = 1 load; B pair of na = 1 load.
// A image: off = ks*512 + w*128 + q*16 + r*4 + s*2 + hi
//   (w = 16-row window, q = row&7, s = (row>>3)&1, k2 = ks*8 + hi*4 + r)
// B image: off = ks*1024 + nw*128 + q*16 + r*4 + s*2 + hi  (n = nw*16+s*8+q)
// smem u32: A0=0(2048) A1=2048 B=4096(12288) SMC=16384(512) tot=16896
// ============================================================================
#define A0O 0
#define A1O 2048
#define BBO 4096
#define SMC 16384
#define SMU 16896

__global__ __launch_bounds__(256, 2) void gemm_fused(
    const float* __restrict__ A, const uint32_t* __restrict__ W,
    uint32_t* __restrict__ out, int M)
{
    extern __shared__ uint32_t sm[];
    const int tid = threadIdx.x, lane = tid & 31;
    const int wid = tid >> 5, wm = wid >> 2, wn = wid & 3;
    const int q = lane >> 2, r = lane & 3;
    const int rowblk = blockIdx.x * 64;
    const uint32_t sbase = smem_u32(sm);

    // ---- group: B chunk0 (3 gates x 4096 u32 = 3072 f4, 12/thread) ----
#pragma unroll
    for (int t = 0; t < 12; t++) {
        int i = tid + t * 256;
        int g = i >> 10, off4 = i & 1023;
        cp_async16(sbase + (BBO + g * 4096 + off4 * 4) * 4,
                   W + g * 8192 + off4 * 4, 16);
    }
    asm volatile("cp.async.commit_group;" ::: "memory");

    // ---- stage epilogue constants (512, 2/thread) ----
#pragma unroll
    for (int t = 0; t < 2; t++) {
        int idx = tid + t * 256;
        int a = idx >> 7, c = idx & 127;
        float v = (a == 0) ? g_cb0[c] : (a == 1) ? g_cb1[c]
                : (a == 2) ? g_cb2[c] : g_wc2[c];
        sm[SMC + idx] = __float_as_uint(v);
    }

    // ---- A: LDG f32 -> f16x2 fragment-image STS, both chunks (8 f4/thr) ----
#pragma unroll
    for (int t = 0; t < 8; t++) {
        int i = tid + t * 256;            // 0..2047
        int row = i >> 5, jj = i & 31;    // row 0..63 local
        int chunk = jj >> 4, j = jj & 15;
        int gr = rowblk + row;
        float4 v = make_float4(0.f, 0.f, 0.f, 0.f);
        if (gr < M) v = *(const float4*)(A + (size_t)gr * 128 + chunk * 64 + j * 4);
        uint32_t base = chunk ? A1O : A0O;
        int rowpart = (row >> 4) * 128 + (row & 7) * 16 + ((row >> 3) & 1) * 2;
#pragma unroll
        for (int e = 0; e < 2; e++) {
            int k2 = 2 * j + e;
            int off = base + (k2 >> 3) * 512 + rowpart + (k2 & 3) * 4 + ((k2 >> 2) & 1);
            sm[off] = e ? pack_f16x2(v.w, v.z) : pack_f16x2(v.y, v.x);
        }
    }

    float C[3][2][4][4];
#pragma unroll
    for (int g = 0; g < 3; g++)
#pragma unroll
        for (int i = 0; i < 2; i++)
#pragma unroll
            for (int j = 0; j < 4; j++)
#pragma unroll
                for (int k = 0; k < 4; k++) C[g][i][j][k] = 0.0f;

    const int fragoff = q * 16 + r * 4;   // common lane offset within a window

    // ================= phase 1 =================
#pragma unroll
    for (int chunk = 0; chunk < 2; chunk++) {
        if (chunk == 1) {
#pragma unroll
            for (int t = 0; t < 12; t++) {
                int i = tid + t * 256;
                int g = i >> 10, off4 = i & 1023;
                cp_async16(sbase + (BBO + g * 4096 + off4 * 4) * 4,
                           W + g * 8192 + 4096 + off4 * 4, 16);
            }
            asm volatile("cp.async.commit_group;" ::: "memory");
        }
        asm volatile("cp.async.wait_group 0;" ::: "memory");
        __syncthreads();
        const uint32_t* Ac = sm + (chunk ? A1O : A0O);
#pragma unroll
        for (int ks = 0; ks < 4; ks++) {
            uint4 af[2];
#pragma unroll
            for (int ma = 0; ma < 2; ma++)
                af[ma] = *(const uint4*)&Ac[ks * 512 + (wm * 2 + ma) * 128 + fragoff];
#pragma unroll
            for (int g = 0; g < 3; g++) {
                const uint32_t* bs = sm + BBO + g * 4096;
#pragma unroll
                for (int p = 0; p < 2; p++) {
                    uint4 bf = *(const uint4*)&bs[ks * 1024 + (wn * 2 + p) * 128 + fragoff];
#pragma unroll
                    for (int ma = 0; ma < 2; ma++) {
                        mma_f16(C[g][ma][2 * p],     af[ma].x, af[ma].z, af[ma].y, af[ma].w, bf.x, bf.y);
                        mma_f16(C[g][ma][2 * p + 1], af[ma].x, af[ma].z, af[ma].y, af[ma].w, bf.z, bf.w);
                    }
                }
            }
        }
        __syncthreads();
    }

    // ---- stream gcn_w (both chunks, 8192 u32 = 2048 f4) into B buffer ----
#pragma unroll
    for (int t = 0; t < 8; t++) {
        int i = tid + t * 256;
        cp_async16(sbase + (BBO + i * 4) * 4, W + 3 * 8192 + i * 4, 16);
    }
    asm volatile("cp.async.commit_group;" ::: "memory");

    // ============ LSTM epilogue -> Hs (f16x2 fragment-image) into A0/A1 =====
#pragma unroll
    for (int ma = 0; ma < 2; ma++) {
#pragma unroll
        for (int half = 0; half < 2; half++) {
            int lrow = wm * 32 + ma * 16 + q + half * 8;
            int rowpart = (lrow >> 4) * 128 + (lrow & 7) * 16 + ((lrow >> 3) & 1) * 2;
#pragma unroll
            for (int na = 0; na < 4; na++) {
                int ch = wn * 32 + na * 8 + 2 * r;
                float hlo, hhi;
                {
                    float zi = C[0][ma][na][half * 2] + __uint_as_float(sm[SMC + ch]);
                    float zc = C[1][ma][na][half * 2] + __uint_as_float(sm[SMC + 128 + ch]);
                    float zo = C[2][ma][na][half * 2] + __uint_as_float(sm[SMC + 256 + ch]);
                    float I = sigfast(zi);
                    float T = tanhfast(zc);
                    float Cs = I * T;
                    float O = sigfast(zo + __uint_as_float(sm[SMC + 384 + ch]) * Cs);
                    hlo = O * tanhfast(Cs);
                }
                {
                    float zi = C[0][ma][na][half * 2 + 1] + __uint_as_float(sm[SMC + ch + 1]);
                    float zc = C[1][ma][na][half * 2 + 1] + __uint_as_float(sm[SMC + 129 + ch]);
                    float zo = C[2][ma][na][half * 2 + 1] + __uint_as_float(sm[SMC + 257 + ch]);
                    float I = sigfast(zi);
                    float T = tanhfast(zc);
                    float Cs = I * T;
                    float O = sigfast(zo + __uint_as_float(sm[SMC + 385 + ch]) * Cs);
                    hhi = O * tanhfast(Cs);
                }
                int k2g = ch >> 1;                // 0..63
                int cchunk = k2g >> 5;
                int k2l = k2g & 31;
                int off = (cchunk ? A1O : A0O) + (k2l >> 3) * 512 + rowpart
                        + (k2l & 3) * 4 + ((k2l >> 2) & 1);
                sm[off] = pack_f16x2(hhi, hlo);
            }
        }
    }
    asm volatile("cp.async.wait_group 0;" ::: "memory");
    __syncthreads();

    // ================= phase 2: hh = Hs @ gcn_w =============================
    float D[2][4][4];
#pragma unroll
    for (int i = 0; i < 2; i++)
#pragma unroll
        for (int j = 0; j < 4; j++)
#pragma unroll
            for (int k = 0; k < 4; k++) D[i][j][k] = 0.0f;

#pragma unroll
    for (int chunk = 0; chunk < 2; chunk++) {
        const uint32_t* as = sm + (chunk ? A1O : A0O);
        const uint32_t* bs = sm + BBO + chunk * 4096;
#pragma unroll
        for (int ks = 0; ks < 4; ks++) {
            uint4 af[2];
#pragma unroll
            for (int ma = 0; ma < 2; ma++)
                af[ma] = *(const uint4*)&as[ks * 512 + (wm * 2 + ma) * 128 + fragoff];
#pragma unroll
            for (int p = 0; p < 2; p++) {
                uint4 bf = *(const uint4*)&bs[ks * 1024 + (wn * 2 + p) * 128 + fragoff];
#pragma unroll
                for (int ma = 0; ma < 2; ma++) {
                    mma_f16(D[ma][2 * p],     af[ma].x, af[ma].z, af[ma].y, af[ma].w, bf.x, bf.y);
                    mma_f16(D[ma][2 * p + 1], af[ma].x, af[ma].z, af[ma].y, af[ma].w, bf.z, bf.w);
                }
            }
        }
    }

    // ---- epilogue 2: write hh as bf16x2 ----
#pragma unroll
    for (int ma = 0; ma < 2; ma++) {
#pragma unroll
        for (int half = 0; half < 2; half++) {
            int row = rowblk + wm * 32 + ma * 16 + q + half * 8;
            if (row >= M) continue;
#pragma unroll
            for (int na = 0; na < 4; na++) {
                int ch = wn * 32 + na * 8 + 2 * r;
                out[(size_t)row * 64 + (ch >> 1)] =
                    pack_bf16x2(D[ma][na][half * 2 + 1], D[ma][na][half * 2]);
            }
        }
    }
}

// ============================================================================
// gather + finalize: warp per node, bf16 hh; cnt from CSR offsets
// ============================================================================
__global__ __launch_bounds__(256) void gather_finalize(const float* __restrict__ gcn_b,
                                                       float* __restrict__ out)
{
    int node = (blockIdx.x * blockDim.x + threadIdx.x) >> 5;
    int lane = threadIdx.x & 31;
    if (node >= N_NODES) return;
    int base = g_off[node];
    int cnt = g_off[node + 1] - base;
    float dgi = g_dg[node];

    const uint2* hh2 = (const uint2*)g_hhb;
    uint2 hv = hh2[(size_t)node * 32 + lane];
    float a0 = dgi * bf_lo(hv.x), a1 = dgi * bf_hi(hv.x);
    float a2 = dgi * bf_lo(hv.y), a3 = dgi * bf_hi(hv.y);

    for (int e0 = 0; e0 < cnt; e0 += 32) {
        int myidx = (e0 + lane < cnt) ? g_csr[base + e0 + lane] : 0;
        int lim = min(32, cnt - e0);
        int t = 0;
        for (; t + 4 <= lim; t += 4) {
            int s0 = __shfl_sync(0xffffffffu, myidx, t);
            int s1 = __shfl_sync(0xffffffffu, myidx, t + 1);
            int s2 = __shfl_sync(0xffffffffu, myidx, t + 2);
            int s3 = __shfl_sync(0xffffffffu, myidx, t + 3);
            float d0 = __ldg(g_dg + s0);
            float d1 = __ldg(g_dg + s1);
            float d2 = __ldg(g_dg + s2);
            float d3 = __ldg(g_dg + s3);
            uint2 v0 = __ldg(hh2 + (size_t)s0 * 32 + lane);
            uint2 v1 = __ldg(hh2 + (size_t)s1 * 32 + lane);
            uint2 v2 = __ldg(hh2 + (size_t)s2 * 32 + lane);
            uint2 v3 = __ldg(hh2 + (size_t)s3 * 32 + lane);
            a0 = fmaf(d0, bf_lo(v0.x), a0); a1 = fmaf(d0, bf_hi(v0.x), a1);
            a2 = fmaf(d0, bf_lo(v0.y), a2); a3 = fmaf(d0, bf_hi(v0.y), a3);
            a0 = fmaf(d1, bf_lo(v1.x), a0); a1 = fmaf(d1, bf_hi(v1.x), a1);
            a2 = fmaf(d1, bf_lo(v1.y), a2); a3 = fmaf(d1, bf_hi(v1.y), a3);
            a0 = fmaf(d2, bf_lo(v2.x), a0); a1 = fmaf(d2, bf_hi(v2.x), a1);
            a2 = fmaf(d2, bf_lo(v2.y), a2); a3 = fmaf(d2, bf_hi(v2.y), a3);
            a0 = fmaf(d3, bf_lo(v3.x), a0); a1 = fmaf(d3, bf_hi(v3.x), a1);
            a2 = fmaf(d3, bf_lo(v3.y), a2); a3 = fmaf(d3, bf_hi(v3.y), a3);
        }
        for (; t < lim; t++) {
            int s = __shfl_sync(0xffffffffu, myidx, t);
            float ds = __ldg(g_dg + s);
            uint2 v = __ldg(hh2 + (size_t)s * 32 + lane);
            a0 = fmaf(ds, bf_lo(v.x), a0);
            a1 = fmaf(ds, bf_hi(v.x), a1);
            a2 = fmaf(ds, bf_lo(v.y), a2);
            a3 = fmaf(ds, bf_hi(v.y), a3);
        }
    }

    float4 gb = ((const float4*)gcn_b)[lane];
    float4 fa = ((const float4*)g_fa)[lane];
    float sum = fmaxf(dgi * a0 + gb.x, 0.0f) * fa.x
              + fmaxf(dgi * a1 + gb.y, 0.0f) * fa.y
              + fmaxf(dgi * a2 + gb.z, 0.0f) * fa.z
              + fmaxf(dgi * a3 + gb.w, 0.0f) * fa.w;
#pragma unroll
    for (int o = 16; o > 0; o >>= 1) sum += __shfl_down_sync(0xffffffffu, sum, o);
    if (lane == 0) out[node] = sum + g_fc;
}

// ============================================================================
// launch. gemm_fused stays the 4th launched kernel for ncu capture.
// ============================================================================
extern "C" void kernel_launch(void* const* d_in, const int* in_sizes, int n_in,
                              void* d_out, int out_size)
{
    const float* x        = (const float*)d_in[0];
    const int*   ei       = (const int*)  d_in[1];
    const float* W_x      = (const float*)d_in[3];
    const float* w_c      = (const float*)d_in[4];
    const float* b        = (const float*)d_in[5];
    const float* theta_b  = (const float*)d_in[7];
    const float* gcn_w    = (const float*)d_in[8];
    const float* gcn_b    = (const float*)d_in[9];
    const float* bn_gamma = (const float*)d_in[10];
    const float* bn_beta  = (const float*)d_in[11];
    const float* bn_mean  = (const float*)d_in[12];
    const float* bn_var   = (const float*)d_in[13];
    const float* lin_w    = (const float*)d_in[14];
    const float* lin_b    = (const float*)d_in[15];
    float* out = (float*)d_out;

    const int* src = ei;
    const int* dst = ei + N_EDGES;

    const int SMF = SMU * 4;  // 67584 B

    static cudaStream_t s1 = nullptr;
    static cudaEvent_t evRoot, evCsr;
    if (!s1) {
        cudaStreamCreateWithFlags(&s1, cudaStreamNonBlocking);
        cudaEventCreateWithFlags(&evRoot, cudaEventDisableTiming);
        cudaEventCreateWithFlags(&evCsr,  cudaEventDisableTiming);
        cudaFuncSetAttribute((const void*)gemm_fused,
                             cudaFuncAttributeMaxDynamicSharedMemorySize, SMF);
    }

    uint32_t *hhp, *wcp;
    cudaGetSymbolAddress((void**)&hhp, g_hhb);
    cudaGetSymbolAddress((void**)&wcp, g_Wc);

    // fork s1 from main at graph root
    cudaEventRecord(evRoot, 0);
    cudaStreamWaitEvent(s1, evRoot, 0);

    prep_all<<<129, 256>>>(W_x, gcn_w, theta_b, b, w_c,                 // #1 (main)
                           bn_gamma, bn_beta, bn_mean, bn_var, lin_w, lin_b);
    count_kernel<<<(N_EDGES + 255) / 256, 256, 0, s1>>>(dst);           // #2 (s1)
    scan_a<<<NB, 256, 0, s1>>>();                                       // #3 (s1)
    gemm_fused<<<(N_NODES + 63) / 64, 256, SMF>>>(x, wcp, hhp, N_NODES); // #4 (main)
    scan_bc<<<NB, 256, 0, s1>>>();                                      // #5 (s1)
    fill_kernel<<<(N_EDGES + 255) / 256, 256, 0, s1>>>(src, dst);       // #6 (s1)
    cudaEventRecord(evCsr, s1);

    // join: gather needs gemm (stream order) + CSR (event)
    cudaStreamWaitEvent(0, evCsr, 0);
    gather_finalize<<<(N_NODES * 32 + 255) / 256, 256>>>(gcn_b, out);   // #7 (main)
}

// round 15
// speedup vs baseline: 1.0169x; 1.0169x over previous
#include <cuda_runtime.h>
#include <cstdint>
#include <math.h>

#define N_NODES 50000
#define N_EDGES 640000
#define NH (N_NODES * 128)
#define NB 196  // ceil(N_NODES / 256)

// ---------------- scratch (static device globals) ---------------------------
// INVARIANT: g_indeg and g_cursor are zero at the start of every kernel_launch
// call: zero-initialized at module load; scan_bc re-zeros g_indeg after
// consuming it and zeroes g_cursor before fill uses it, every run.
__device__ uint32_t g_hhb[NH / 2];    // Hs @ gcn_w (unscaled), bf16x2 packed
// f16x2 weights as uint2-fragment image (R13 layout), per matrix (i,c,o,gcn):
// i = m*8192 + c*4096 + ks*1024 + n*8 + rr*2 + slot
// where k2 = c*32 + ks*8 + slot*4 + rr ; u32 = {W[2k2][n] lo, W[2k2+1][n] hi}
__device__ uint32_t g_Wc[4 * 8192];
__device__ int   g_indeg[N_NODES];
__device__ float g_dg[N_NODES];       // rsqrt(1 + indeg)
__device__ int   g_off[N_NODES + 1];
__device__ int   g_cursor[N_NODES];
__device__ int   g_csr[N_EDGES];
__device__ int   g_part[256];
// fused per-channel constants
__device__ float g_cb0[128], g_cb1[128], g_cb2[128], g_wc2[128];
__device__ float g_fa[128];
__device__ float g_fc;

// ---------------- helpers ----------------------------------------------------
__device__ __forceinline__ float tanhfast(float x) {
    float r; asm("tanh.approx.f32 %0, %1;" : "=f"(r) : "f"(x)); return r;
}
__device__ __forceinline__ float sigfast(float x) {
    return 0.5f * tanhfast(0.5f * x) + 0.5f;
}
__device__ __forceinline__ uint32_t pack_bf16x2(float hi, float lo) {
    uint32_t u; asm("cvt.rn.bf16x2.f32 %0, %1, %2;" : "=r"(u) : "f"(hi), "f"(lo)); return u;
}
__device__ __forceinline__ uint32_t pack_f16x2(float hi, float lo) {
    uint32_t u; asm("cvt.rn.f16x2.f32 %0, %1, %2;" : "=r"(u) : "f"(hi), "f"(lo)); return u;
}
__device__ __forceinline__ float bf_lo(uint32_t u) { return __uint_as_float(u << 16); }
__device__ __forceinline__ float bf_hi(uint32_t u) { return __uint_as_float(u & 0xffff0000u); }
__device__ __forceinline__ void mma_f16(float* d, const uint32_t* a, uint32_t b0, uint32_t b1) {
    asm volatile(
        "mma.sync.aligned.m16n8k16.row.col.f32.f16.f16.f32 "
        "{%0,%1,%2,%3}, {%4,%5,%6,%7}, {%8,%9}, {%0,%1,%2,%3};"
        : "+f"(d[0]), "+f"(d[1]), "+f"(d[2]), "+f"(d[3])
        : "r"(a[0]), "r"(a[1]), "r"(a[2]), "r"(a[3]), "r"(b0), "r"(b1));
}
__device__ __forceinline__ uint32_t smem_u32(const void* p) {
    uint32_t a;
    asm("{ .reg .u64 t; cvta.to.shared.u64 t, %1; cvt.u32.u64 %0, t; }" : "=r"(a) : "l"(p));
    return a;
}
__device__ __forceinline__ void cp_async16(uint32_t daddr, const void* saddr, int srcsz) {
    asm volatile("cp.async.cg.shared.global [%0], [%1], 16, %2;"
                 :: "r"(daddr), "l"(saddr), "r"(srcsz) : "memory");
}

// ---------------- prep: weights -> uint2 fragment image + constants ----------
__global__ void prep_all(const float* __restrict__ Wx, const float* __restrict__ gcn,
                         const float* __restrict__ theta_b, const float* __restrict__ b,
                         const float* __restrict__ w_c,
                         const float* __restrict__ gamma, const float* __restrict__ beta,
                         const float* __restrict__ mean, const float* __restrict__ var,
                         const float* __restrict__ lin_w, const float* __restrict__ lin_b) {
    if (blockIdx.x < 128) {
        int i = blockIdx.x * 256 + threadIdx.x;   // 0..32767
        int m = i >> 13, rem = i & 8191;
        int c = rem >> 12;
        int rem2 = rem & 4095;
        int ks = rem2 >> 10;
        int t = rem2 & 1023;
        int n = t >> 3;
        int u = t & 7;
        int rr = u >> 1, slot = u & 1;
        int k2 = c * 32 + ks * 8 + slot * 4 + rr;
        const float* S = (m == 0) ? Wx
                       : (m == 1) ? Wx + 2 * 16384
                       : (m == 2) ? Wx + 3 * 16384 : gcn;
        g_Wc[i] = pack_f16x2(S[(2 * k2 + 1) * 128 + n], S[2 * k2 * 128 + n]);
        return;
    }
    int ch = threadIdx.x;
    if (ch >= 128) return;
    g_cb0[ch] = theta_b[ch] + b[ch];
    g_cb1[ch] = theta_b[256 + ch] + b[256 + ch];
    g_cb2[ch] = theta_b[384 + ch] + b[384 + ch];
    g_wc2[ch] = w_c[256 + ch];
    float sc = gamma[ch] * rsqrtf(var[ch] + 1e-5f);
    g_fa[ch] = sc * lin_w[ch];
    __shared__ float red[128];
    red[ch] = (beta[ch] - mean[ch] * sc) * lin_w[ch];
    __syncthreads();
    for (int o = 64; o > 0; o >>= 1) { if (ch < o) red[ch] += red[ch + o]; __syncthreads(); }
    if (ch == 0) g_fc = red[0] + lin_b[0];
}

__global__ void count_kernel(const int* __restrict__ dst) {
    int e = blockIdx.x * blockDim.x + threadIdx.x;
    if (e < N_EDGES) atomicAdd(&g_indeg[dst[e]], 1);
}

// ---- scan stage A ----
__global__ __launch_bounds__(256) void scan_a() {
    int i = blockIdx.x * 256 + threadIdx.x;
    int v = (i < N_NODES) ? g_indeg[i] : 0;
    int lane = threadIdx.x & 31, warp = threadIdx.x >> 5;
#pragma unroll
    for (int o = 16; o > 0; o >>= 1) v += __shfl_down_sync(0xffffffffu, v, o);
    __shared__ int ws[8];
    if (lane == 0) ws[warp] = v;
    __syncthreads();
    if (threadIdx.x == 0) {
        int s = 0;
#pragma unroll
        for (int w = 0; w < 8; w++) s += ws[w];
        g_part[blockIdx.x] = s;
    }
}
// ---- scan stage BC ----
__global__ __launch_bounds__(256) void scan_bc() {
    int t = threadIdx.x, lane = t & 31, warp = t >> 5;
    __shared__ int s2[256];
    __shared__ int ws[8];
    {
        int v = (t < NB) ? g_part[t] : 0;
        int x = v;
#pragma unroll
        for (int o = 1; o < 32; o <<= 1) {
            int y = __shfl_up_sync(0xffffffffu, x, o);
            if (lane >= o) x += y;
        }
        if (lane == 31) ws[warp] = x;
        __syncthreads();
        if (warp == 0 && lane < 8) {
            int w = ws[lane];
#pragma unroll
            for (int o = 1; o < 8; o <<= 1) {
                int y = __shfl_up_sync(0xffu, w, o);
                if (lane >= o) w += y;
            }
            ws[lane] = w;
        }
        __syncthreads();
        s2[t] = x + (warp > 0 ? ws[warp - 1] : 0);
        __syncthreads();
    }
    int blockbase = (blockIdx.x == 0) ? 0 : s2[blockIdx.x - 1];
    __syncthreads();
    int i = blockIdx.x * 256 + t;
    int v = (i < N_NODES) ? g_indeg[i] : 0;
    int x = v;
#pragma unroll
    for (int o = 1; o < 32; o <<= 1) {
        int y = __shfl_up_sync(0xffffffffu, x, o);
        if (lane >= o) x += y;
    }
    if (lane == 31) ws[warp] = x;
    __syncthreads();
    if (warp == 0 && lane < 8) {
        int w = ws[lane];
#pragma unroll
        for (int o = 1; o < 8; o <<= 1) {
            int y = __shfl_up_sync(0xffu, w, o);
            if (lane >= o) w += y;
        }
        ws[lane] = w;
    }
    __syncthreads();
    if (i < N_NODES) {
        g_off[i] = x - v + (warp > 0 ? ws[warp - 1] : 0) + blockbase;
        g_dg[i] = rsqrtf(1.0f + (float)v);
        g_cursor[i] = 0;
        g_indeg[i] = 0;  // restore invariant for next replay
    }
    if (blockIdx.x == 0 && t == 0) g_off[N_NODES] = N_EDGES;
}

__global__ void fill_kernel(const int* __restrict__ src, const int* __restrict__ dst) {
    int e = blockIdx.x * blockDim.x + threadIdx.x;
    if (e >= N_EDGES) return;
    int d = dst[e];
    g_csr[g_off[d] + atomicAdd(&g_cursor[d], 1)] = src[e];
}

// ============================================================================
// Fused f16-MMA GEMM, 256 threads, M-tile 64, 8 warps (2m x 4n), tile 32x32.
// 2 CTAs/SM. Double-buffered B: all B cp.asyncs issued up front; gcn_w
// streams into B0's space during chunk-1 compute. Zero exposed load latency.
// smem u32: A0=0(2048) A1=2048(2048) B0=4096(12288) B1=16384(12288) tot=28672
// ============================================================================
#define A0O 0
#define A1O 2048
#define B0O 4096
#define B1O 16384
#define SMU 28672

__global__ __launch_bounds__(256, 2) void gemm_fused(
    const float* __restrict__ A, const uint32_t* __restrict__ W,
    uint32_t* __restrict__ out, int M)
{
    extern __shared__ uint32_t sm[];
    const int tid = threadIdx.x, lane = tid & 31;
    const int wid = tid >> 5, wm = wid >> 2, wn = wid & 3;
    const int q = lane >> 2, r = lane & 3;
    const int rowblk = blockIdx.x * 64;
    const uint32_t sbase = smem_u32(sm);

    // ---- issue A LDGs early (guarded, into regs) ----
    float4 av[8];
#pragma unroll
    for (int t = 0; t < 8; t++) {
        int i = tid + t * 256;            // 0..2047
        int row = i >> 5, jj = i & 31;
        int chunk = jj >> 4, j = jj & 15;
        int gr = rowblk + row;
        av[t] = make_float4(0.f, 0.f, 0.f, 0.f);
        if (gr < M) av[t] = *(const float4*)(A + (size_t)gr * 128 + chunk * 64 + j * 4);
    }

    // ---- group 1: B chunk0 (3 gates x 4096 u32 = 3072 f4, 12/thread) ----
#pragma unroll
    for (int t = 0; t < 12; t++) {
        int i = tid + t * 256;
        int g = i >> 10, off4 = i & 1023;
        cp_async16(sbase + (B0O + g * 4096 + off4 * 4) * 4,
                   W + g * 8192 + off4 * 4, 16);
    }
    asm volatile("cp.async.commit_group;" ::: "memory");
    // ---- group 2: B chunk1 into B1 ----
#pragma unroll
    for (int t = 0; t < 12; t++) {
        int i = tid + t * 256;
        int g = i >> 10, off4 = i & 1023;
        cp_async16(sbase + (B1O + g * 4096 + off4 * 4) * 4,
                   W + g * 8192 + 4096 + off4 * 4, 16);
    }
    asm volatile("cp.async.commit_group;" ::: "memory");

    // ---- A: cvt + STS fragment image, both chunks ----
#pragma unroll
    for (int t = 0; t < 8; t++) {
        int i = tid + t * 256;
        int row = i >> 5, jj = i & 31;
        int chunk = jj >> 4, j = jj & 15;
        uint32_t base = chunk ? A1O : A0O;
        int k2a = 2 * j, k2b = 2 * j + 1;
        int oa = base + (k2a >> 3) * 512 + row * 8 + (k2a & 3) * 2 + ((k2a >> 2) & 1);
        int ob = base + (k2b >> 3) * 512 + row * 8 + (k2b & 3) * 2 + ((k2b >> 2) & 1);
        sm[oa] = pack_f16x2(av[t].y, av[t].x);
        sm[ob] = pack_f16x2(av[t].w, av[t].z);
    }

    float C[3][2][4][4];
#pragma unroll
    for (int g = 0; g < 3; g++)
#pragma unroll
        for (int i = 0; i < 2; i++)
#pragma unroll
            for (int j = 0; j < 4; j++)
#pragma unroll
                for (int k = 0; k < 4; k++) C[g][i][j][k] = 0.0f;

    // ================= phase 1, chunk 0 =================
    asm volatile("cp.async.wait_group 1;" ::: "memory");  // B0 done (B1 in flight)
    __syncthreads();
#pragma unroll
    for (int ks = 0; ks < 4; ks++) {
        uint32_t a[2][4];
#pragma unroll
        for (int ma = 0; ma < 2; ma++) {
            int m = wm * 32 + ma * 16 + q;
            uint2 lo = *(const uint2*)&sm[A0O + ks * 512 + m * 8 + r * 2];
            uint2 hi = *(const uint2*)&sm[A0O + ks * 512 + (m + 8) * 8 + r * 2];
            a[ma][0] = lo.x; a[ma][2] = lo.y;
            a[ma][1] = hi.x; a[ma][3] = hi.y;
        }
#pragma unroll
        for (int g = 0; g < 3; g++) {
            const uint32_t* bs = sm + B0O + g * 4096;
#pragma unroll
            for (int na = 0; na < 4; na++) {
                int n = wn * 32 + na * 8 + q;
                uint2 b = *(const uint2*)&bs[ks * 1024 + n * 8 + r * 2];
#pragma unroll
                for (int ma = 0; ma < 2; ma++) mma_f16(C[g][ma][na], a[ma], b.x, b.y);
            }
        }
    }
    __syncthreads();  // B0 reads done; safe to overwrite with gcn_w

    // ---- group 3: gcn_w (8192 u32 = 2048 f4) into B0 space ----
#pragma unroll
    for (int t = 0; t < 8; t++) {
        int i = tid + t * 256;
        cp_async16(sbase + (B0O + i * 4) * 4, W + 3 * 8192 + i * 4, 16);
    }
    asm volatile("cp.async.commit_group;" ::: "memory");

    // ================= phase 1, chunk 1 =================
    asm volatile("cp.async.wait_group 1;" ::: "memory");  // B1 done (gcn_w in flight)
    __syncthreads();
#pragma unroll
    for (int ks = 0; ks < 4; ks++) {
        uint32_t a[2][4];
#pragma unroll
        for (int ma = 0; ma < 2; ma++) {
            int m = wm * 32 + ma * 16 + q;
            uint2 lo = *(const uint2*)&sm[A1O + ks * 512 + m * 8 + r * 2];
            uint2 hi = *(const uint2*)&sm[A1O + ks * 512 + (m + 8) * 8 + r * 2];
            a[ma][0] = lo.x; a[ma][2] = lo.y;
            a[ma][1] = hi.x; a[ma][3] = hi.y;
        }
#pragma unroll
        for (int g = 0; g < 3; g++) {
            const uint32_t* bs = sm + B1O + g * 4096;
#pragma unroll
            for (int na = 0; na < 4; na++) {
                int n = wn * 32 + na * 8 + q;
                uint2 b = *(const uint2*)&bs[ks * 1024 + n * 8 + r * 2];
#pragma unroll
                for (int ma = 0; ma < 2; ma++) mma_f16(C[g][ma][na], a[ma], b.x, b.y);
            }
        }
    }
    __syncthreads();  // all phase-1 reads of A0/A1 done before Hs overwrite

    // ============ LSTM epilogue -> Hs (f16x2 fragment-image) into A0/A1 =====
#pragma unroll
    for (int ma = 0; ma < 2; ma++) {
#pragma unroll
        for (int half = 0; half < 2; half++) {
            int lrow = wm * 32 + ma * 16 + q + half * 8;
#pragma unroll
            for (int na = 0; na < 4; na++) {
                int ch = wn * 32 + na * 8 + 2 * r;
                float hlo, hhi;
                {
                    float zi = C[0][ma][na][half * 2] + __ldg(g_cb0 + ch);
                    float zc = C[1][ma][na][half * 2] + __ldg(g_cb1 + ch);
                    float zo = C[2][ma][na][half * 2] + __ldg(g_cb2 + ch);
                    float I = sigfast(zi);
                    float T = tanhfast(zc);
                    float Cs = I * T;
                    float O = sigfast(zo + __ldg(g_wc2 + ch) * Cs);
                    hlo = O * tanhfast(Cs);
                }
                {
                    float zi = C[0][ma][na][half * 2 + 1] + __ldg(g_cb0 + ch + 1);
                    float zc = C[1][ma][na][half * 2 + 1] + __ldg(g_cb1 + ch + 1);
                    float zo = C[2][ma][na][half * 2 + 1] + __ldg(g_cb2 + ch + 1);
                    float I = sigfast(zi);
                    float T = tanhfast(zc);
                    float Cs = I * T;
                    float O = sigfast(zo + __ldg(g_wc2 + ch + 1) * Cs);
                    hhi = O * tanhfast(Cs);
                }
                int k2 = ch >> 1;                 // 0..63
                int cchunk = k2 >> 5;
                int k2l = k2 & 31;
                int off = (cchunk ? A1O : A0O) + (k2l >> 3) * 512 + lrow * 8
                        + (k2l & 3) * 2 + ((k2l >> 2) & 1);
                sm[off] = pack_f16x2(hhi, hlo);
            }
        }
    }
    asm volatile("cp.async.wait_group 0;" ::: "memory");  // gcn_w ready
    __syncthreads();

    // ================= phase 2: hh = Hs @ gcn_w (gcn_w image in B0 space) ===
    float D[2][4][4];
#pragma unroll
    for (int i = 0; i < 2; i++)
#pragma unroll
        for (int j = 0; j < 4; j++)
#pragma unroll
            for (int k = 0; k < 4; k++) D[i][j][k] = 0.0f;

#pragma unroll
    for (int chunk = 0; chunk < 2; chunk++) {
        const uint32_t* as = sm + (chunk ? A1O : A0O);
        const uint32_t* bs = sm + B0O + chunk * 4096;
#pragma unroll
        for (int ks = 0; ks < 4; ks++) {
            uint32_t a[2][4];
#pragma unroll
            for (int ma = 0; ma < 2; ma++) {
                int m = wm * 32 + ma * 16 + q;
                uint2 lo = *(const uint2*)&as[ks * 512 + m * 8 + r * 2];
                uint2 hi = *(const uint2*)&as[ks * 512 + (m + 8) * 8 + r * 2];
                a[ma][0] = lo.x; a[ma][2] = lo.y;
                a[ma][1] = hi.x; a[ma][3] = hi.y;
            }
#pragma unroll
            for (int na = 0; na < 4; na++) {
                int n = wn * 32 + na * 8 + q;
                uint2 b = *(const uint2*)&bs[ks * 1024 + n * 8 + r * 2];
#pragma unroll
                for (int ma = 0; ma < 2; ma++) mma_f16(D[ma][na], a[ma], b.x, b.y);
            }
        }
    }

    // ---- epilogue 2: write hh as bf16x2 ----
#pragma unroll
    for (int ma = 0; ma < 2; ma++) {
#pragma unroll
        for (int half = 0; half < 2; half++) {
            int row = rowblk + wm * 32 + ma * 16 + q + half * 8;
            if (row >= M) continue;
#pragma unroll
            for (int na = 0; na < 4; na++) {
                int ch = wn * 32 + na * 8 + 2 * r;
                out[(size_t)row * 64 + (ch >> 1)] =
                    pack_bf16x2(D[ma][na][half * 2 + 1], D[ma][na][half * 2]);
            }
        }
    }
}

// ============================================================================
// gather + finalize: warp per node, bf16 hh, unroll-by-8 for MLP
// ============================================================================
__global__ __launch_bounds__(256) void gather_finalize(const float* __restrict__ gcn_b,
                                                       float* __restrict__ out)
{
    int node = (blockIdx.x * blockDim.x + threadIdx.x) >> 5;
    int lane = threadIdx.x & 31;
    if (node >= N_NODES) return;
    int base = g_off[node];
    int cnt = g_off[node + 1] - base;
    float dgi = g_dg[node];

    const uint2* hh2 = (const uint2*)g_hhb;
    uint2 hv = hh2[(size_t)node * 32 + lane];
    float a0 = dgi * bf_lo(hv.x), a1 = dgi * bf_hi(hv.x);
    float a2 = dgi * bf_lo(hv.y), a3 = dgi * bf_hi(hv.y);

    for (int e0 = 0; e0 < cnt; e0 += 32) {
        int myidx = (e0 + lane < cnt) ? g_csr[base + e0 + lane] : 0;
        int lim = min(32, cnt - e0);
        int t = 0;
        for (; t + 8 <= lim; t += 8) {
            int s[8];
#pragma unroll
            for (int u = 0; u < 8; u++) s[u] = __shfl_sync(0xffffffffu, myidx, t + u);
            float d[8];
#pragma unroll
            for (int u = 0; u < 8; u++) d[u] = __ldg(g_dg + s[u]);
            uint2 v[8];
#pragma unroll
            for (int u = 0; u < 8; u++) v[u] = __ldg(hh2 + (size_t)s[u] * 32 + lane);
#pragma unroll
            for (int u = 0; u < 8; u++) {
                a0 = fmaf(d[u], bf_lo(v[u].x), a0);
                a1 = fmaf(d[u], bf_hi(v[u].x), a1);
                a2 = fmaf(d[u], bf_lo(v[u].y), a2);
                a3 = fmaf(d[u], bf_hi(v[u].y), a3);
            }
        }
        for (; t < lim; t++) {
            int s = __shfl_sync(0xffffffffu, myidx, t);
            float ds = __ldg(g_dg + s);
            uint2 v = __ldg(hh2 + (size_t)s * 32 + lane);
            a0 = fmaf(ds, bf_lo(v.x), a0);
            a1 = fmaf(ds, bf_hi(v.x), a1);
            a2 = fmaf(ds, bf_lo(v.y), a2);
            a3 = fmaf(ds, bf_hi(v.y), a3);
        }
    }

    float4 gb = ((const float4*)gcn_b)[lane];
    float4 fa = ((const float4*)g_fa)[lane];
    float sum = fmaxf(dgi * a0 + gb.x, 0.0f) * fa.x
              + fmaxf(dgi * a1 + gb.y, 0.0f) * fa.y
              + fmaxf(dgi * a2 + gb.z, 0.0f) * fa.z
              + fmaxf(dgi * a3 + gb.w, 0.0f) * fa.w;
#pragma unroll
    for (int o = 16; o > 0; o >>= 1) sum += __shfl_down_sync(0xffffffffu, sum, o);
    if (lane == 0) out[node] = sum + g_fc;
}

// ============================================================================
// launch. gemm_fused stays the 4th launched kernel for ncu capture.
// ============================================================================
extern "C" void kernel_launch(void* const* d_in, const int* in_sizes, int n_in,
                              void* d_out, int out_size)
{
    const float* x        = (const float*)d_in[0];
    const int*   ei       = (const int*)  d_in[1];
    const float* W_x      = (const float*)d_in[3];
    const float* w_c      = (const float*)d_in[4];
    const float* b        = (const float*)d_in[5];
    const float* theta_b  = (const float*)d_in[7];
    const float* gcn_w    = (const float*)d_in[8];
    const float* gcn_b    = (const float*)d_in[9];
    const float* bn_gamma = (const float*)d_in[10];
    const float* bn_beta  = (const float*)d_in[11];
    const float* bn_mean  = (const float*)d_in[12];
    const float* bn_var   = (const float*)d_in[13];
    const float* lin_w    = (const float*)d_in[14];
    const float* lin_b    = (const float*)d_in[15];
    float* out = (float*)d_out;

    const int* src = ei;
    const int* dst = ei + N_EDGES;

    const int SMF = SMU * 4;  // 114688 B

    static cudaStream_t s1 = nullptr;
    static cudaEvent_t evRoot, evCsr;
    if (!s1) {
        cudaStreamCreateWithFlags(&s1, cudaStreamNonBlocking);
        cudaEventCreateWithFlags(&evRoot, cudaEventDisableTiming);
        cudaEventCreateWithFlags(&evCsr,  cudaEventDisableTiming);
        cudaFuncSetAttribute((const void*)gemm_fused,
                             cudaFuncAttributeMaxDynamicSharedMemorySize, SMF);
    }

    uint32_t *hhp, *wcp;
    cudaGetSymbolAddress((void**)&hhp, g_hhb);
    cudaGetSymbolAddress((void**)&wcp, g_Wc);

    // fork s1 from main at graph root
    cudaEventRecord(evRoot, 0);
    cudaStreamWaitEvent(s1, evRoot, 0);

    prep_all<<<129, 256>>>(W_x, gcn_w, theta_b, b, w_c,                 // #1 (main)
                           bn_gamma, bn_beta, bn_mean, bn_var, lin_w, lin_b);
    count_kernel<<<(N_EDGES + 255) / 256, 256, 0, s1>>>(dst);           // #2 (s1)
    scan_a<<<NB, 256, 0, s1>>>();                                       // #3 (s1)
    gemm_fused<<<(N_NODES + 63) / 64, 256, SMF>>>(x, wcp, hhp, N_NODES); // #4 (main)
    scan_bc<<<NB, 256, 0, s1>>>();                                      // #5 (s1)
    fill_kernel<<<(N_EDGES + 255) / 256, 256, 0, s1>>>(src, dst);       // #6 (s1)
    cudaEventRecord(evCsr, s1);

    // join: gather needs gemm (stream order) + CSR (event)
    cudaStreamWaitEvent(0, evCsr, 0);
    gather_finalize<<<(N_NODES * 32 + 255) / 256, 256>>>(gcn_b, out);   // #7 (main)
}

// round 16
// speedup vs baseline: 1.0242x; 1.0072x over previous
#include <cuda_runtime.h>
#include <cuda_fp16.h>
#include <cstdint>
#include <math.h>

#define N_NODES 50000
#define N_EDGES 640000
#define NH (N_NODES * 128)
#define NB 196  // ceil(N_NODES / 256)

// ---------------- scratch (static device globals) ---------------------------
// INVARIANT: g_indeg and g_cursor are zero at the start of every kernel_launch
// call: zero-initialized at module load; scan_bc re-zeros g_indeg after
// consuming it and zeroes g_cursor before fill uses it, every run.
__device__ uint32_t g_hhb[NH / 2];    // Hs @ gcn_w (unscaled), bf16x2 packed
// f16x2 weights as uint2-fragment image, per matrix (i,c,o,gcn):
// img = m*8192 + c*4096 + ks*1024 + n*8 + rr*2 + slot
// where k2 = c*32 + ks*8 + slot*4 + rr ; u32 = {W[2k2][n] lo, W[2k2+1][n] hi}
__device__ uint32_t g_Wc[4 * 8192];
__device__ int   g_indeg[N_NODES];
__device__ float g_dg[N_NODES];       // rsqrt(1 + indeg)
__device__ int   g_off[N_NODES + 1];
__device__ int   g_cursor[N_NODES];
__device__ int   g_csr[N_EDGES];
__device__ int   g_part[256];
// fused per-channel constants
__device__ float g_cb0[128], g_cb1[128], g_cb2[128], g_wc2[128];
__device__ float g_fa[128];
__device__ float g_fc;

// ---------------- helpers ----------------------------------------------------
__device__ __forceinline__ float tanhfast(float x) {
    float r; asm("tanh.approx.f32 %0, %1;" : "=f"(r) : "f"(x)); return r;
}
__device__ __forceinline__ float sigfast(float x) {
    return 0.5f * tanhfast(0.5f * x) + 0.5f;
}
__device__ __forceinline__ uint32_t pack_bf16x2(float hi, float lo) {
    uint32_t u; asm("cvt.rn.bf16x2.f32 %0, %1, %2;" : "=r"(u) : "f"(hi), "f"(lo)); return u;
}
__device__ __forceinline__ uint32_t pack_f16x2(float hi, float lo) {
    uint32_t u; asm("cvt.rn.f16x2.f32 %0, %1, %2;" : "=r"(u) : "f"(hi), "f"(lo)); return u;
}
__device__ __forceinline__ float2 unpack_f16x2(uint32_t u) {
    __half2 h = *reinterpret_cast<__half2*>(&u);
    return __half22float2(h);
}
__device__ __forceinline__ float bf_lo(uint32_t u) { return __uint_as_float(u << 16); }
__device__ __forceinline__ float bf_hi(uint32_t u) { return __uint_as_float(u & 0xffff0000u); }
// f16-accumulator MMA: D(f16x2 pair) += A(f16) * B(f16), m16n8k16, row.col
__device__ __forceinline__ void mma_f16a(uint32_t* d, const uint32_t* a,
                                         uint32_t b0, uint32_t b1) {
    asm volatile(
        "mma.sync.aligned.m16n8k16.row.col.f16.f16.f16.f16 "
        "{%0,%1}, {%2,%3,%4,%5}, {%6,%7}, {%0,%1};"
        : "+r"(d[0]), "+r"(d[1])
        : "r"(a[0]), "r"(a[1]), "r"(a[2]), "r"(a[3]), "r"(b0), "r"(b1));
}
__device__ __forceinline__ uint32_t smem_u32(const void* p) {
    uint32_t a;
    asm("{ .reg .u64 t; cvta.to.shared.u64 t, %1; cvt.u32.u64 %0, t; }" : "=r"(a) : "l"(p));
    return a;
}
__device__ __forceinline__ void cp_async16(uint32_t daddr, const void* saddr, int srcsz) {
    asm volatile("cp.async.cg.shared.global [%0], [%1], 16, %2;"
                 :: "r"(daddr), "l"(saddr), "r"(srcsz) : "memory");
}

// ---------------- prep: weights -> fragment image (coalesced) + constants ----
__global__ void prep_all(const float* __restrict__ Wx, const float* __restrict__ gcn,
                         const float* __restrict__ theta_b, const float* __restrict__ b,
                         const float* __restrict__ w_c,
                         const float* __restrict__ gamma, const float* __restrict__ beta,
                         const float* __restrict__ mean, const float* __restrict__ var,
                         const float* __restrict__ lin_w, const float* __restrict__ lin_b) {
    if (blockIdx.x < 128) {
        int i = blockIdx.x * 256 + threadIdx.x;   // 0..32767, n fastest -> coalesced reads
        int m  = i >> 13;
        int c  = (i >> 12) & 1;
        int ks = (i >> 10) & 3;
        int u  = (i >> 7) & 7;
        int n  = i & 127;
        int rr = u >> 1, slot = u & 1;
        int k2 = c * 32 + ks * 8 + slot * 4 + rr;
        const float* S = (m == 0) ? Wx
                       : (m == 1) ? Wx + 2 * 16384
                       : (m == 2) ? Wx + 3 * 16384 : gcn;
        uint32_t img = (uint32_t)(m * 8192 + c * 4096 + ks * 1024 + n * 8 + u);
        g_Wc[img] = pack_f16x2(S[(2 * k2 + 1) * 128 + n], S[2 * k2 * 128 + n]);
        return;
    }
    int ch = threadIdx.x;
    if (ch >= 128) return;
    g_cb0[ch] = theta_b[ch] + b[ch];
    g_cb1[ch] = theta_b[256 + ch] + b[256 + ch];
    g_cb2[ch] = theta_b[384 + ch] + b[384 + ch];
    g_wc2[ch] = w_c[256 + ch];
    float sc = gamma[ch] * rsqrtf(var[ch] + 1e-5f);
    g_fa[ch] = sc * lin_w[ch];
    __shared__ float red[128];
    red[ch] = (beta[ch] - mean[ch] * sc) * lin_w[ch];
    __syncthreads();
    for (int o = 64; o > 0; o >>= 1) { if (ch < o) red[ch] += red[ch + o]; __syncthreads(); }
    if (ch == 0) g_fc = red[0] + lin_b[0];
}

__global__ void count_kernel(const int* __restrict__ dst) {
    int e = blockIdx.x * blockDim.x + threadIdx.x;
    if (e < N_EDGES) atomicAdd(&g_indeg[dst[e]], 1);
}

// ---- scan stage A ----
__global__ __launch_bounds__(256) void scan_a() {
    int i = blockIdx.x * 256 + threadIdx.x;
    int v = (i < N_NODES) ? g_indeg[i] : 0;
    int lane = threadIdx.x & 31, warp = threadIdx.x >> 5;
#pragma unroll
    for (int o = 16; o > 0; o >>= 1) v += __shfl_down_sync(0xffffffffu, v, o);
    __shared__ int ws[8];
    if (lane == 0) ws[warp] = v;
    __syncthreads();
    if (threadIdx.x == 0) {
        int s = 0;
#pragma unroll
        for (int w = 0; w < 8; w++) s += ws[w];
        g_part[blockIdx.x] = s;
    }
}
// ---- scan stage BC ----
__global__ __launch_bounds__(256) void scan_bc() {
    int t = threadIdx.x, lane = t & 31, warp = t >> 5;
    __shared__ int s2[256];
    __shared__ int ws[8];
    {
        int v = (t < NB) ? g_part[t] : 0;
        int x = v;
#pragma unroll
        for (int o = 1; o < 32; o <<= 1) {
            int y = __shfl_up_sync(0xffffffffu, x, o);
            if (lane >= o) x += y;
        }
        if (lane == 31) ws[warp] = x;
        __syncthreads();
        if (warp == 0 && lane < 8) {
            int w = ws[lane];
#pragma unroll
            for (int o = 1; o < 8; o <<= 1) {
                int y = __shfl_up_sync(0xffu, w, o);
                if (lane >= o) w += y;
            }
            ws[lane] = w;
        }
        __syncthreads();
        s2[t] = x + (warp > 0 ? ws[warp - 1] : 0);
        __syncthreads();
    }
    int blockbase = (blockIdx.x == 0) ? 0 : s2[blockIdx.x - 1];
    __syncthreads();
    int i = blockIdx.x * 256 + t;
    int v = (i < N_NODES) ? g_indeg[i] : 0;
    int x = v;
#pragma unroll
    for (int o = 1; o < 32; o <<= 1) {
        int y = __shfl_up_sync(0xffffffffu, x, o);
        if (lane >= o) x += y;
    }
    if (lane == 31) ws[warp] = x;
    __syncthreads();
    if (warp == 0 && lane < 8) {
        int w = ws[lane];
#pragma unroll
        for (int o = 1; o < 8; o <<= 1) {
            int y = __shfl_up_sync(0xffu, w, o);
            if (lane >= o) w += y;
        }
        ws[lane] = w;
    }
    __syncthreads();
    if (i < N_NODES) {
        g_off[i] = x - v + (warp > 0 ? ws[warp - 1] : 0) + blockbase;
        g_dg[i] = rsqrtf(1.0f + (float)v);
        g_cursor[i] = 0;
        g_indeg[i] = 0;  // restore invariant for next replay
    }
    if (blockIdx.x == 0 && t == 0) g_off[N_NODES] = N_EDGES;
}

__global__ void fill_kernel(const int* __restrict__ src, const int* __restrict__ dst) {
    int e = blockIdx.x * blockDim.x + threadIdx.x;
    if (e >= N_EDGES) return;
    int d = dst[e];
    g_csr[g_off[d] + atomicAdd(&g_cursor[d], 1)] = src[e];
}

// ============================================================================
// Fused f16-MMA GEMM with f16 ACCUMULATORS, 256 threads, M-tile 64,
// 8 warps (2m x 4n), warp tile 32x32, 3 CTAs/SM (acc regs halved).
// Single B buffer sequenced B0 -> B1 -> gcn_w (3 CTAs interleave the waits).
// smem u32: A0=0(2048) A1=2048(2048) B=4096(12288) tot=16384 (64KB)
// ============================================================================
#define A0O 0
#define A1O 2048
#define BBO 4096
#define SMU 16384

__global__ __launch_bounds__(256, 3) void gemm_fused(
    const float* __restrict__ A, const uint32_t* __restrict__ W,
    uint32_t* __restrict__ out, int M)
{
    extern __shared__ uint32_t sm[];
    const int tid = threadIdx.x, lane = tid & 31;
    const int wid = tid >> 5, wm = wid >> 2, wn = wid & 3;
    const int q = lane >> 2, r = lane & 3;
    const int rowblk = blockIdx.x * 64;
    const uint32_t sbase = smem_u32(sm);

    // ---- B chunk0 (3 gates x 4096 u32 = 3072 f4, 12/thread) ----
#pragma unroll
    for (int t = 0; t < 12; t++) {
        int i = tid + t * 256;
        int g = i >> 10, off4 = i & 1023;
        cp_async16(sbase + (BBO + g * 4096 + off4 * 4) * 4,
                   W + g * 8192 + off4 * 4, 16);
    }
    asm volatile("cp.async.commit_group;" ::: "memory");

    // ---- A: LDG f32 -> f16x2 fragment-image STS, both chunks ----
#pragma unroll
    for (int t = 0; t < 8; t++) {
        int i = tid + t * 256;            // 0..2047
        int row = i >> 5, jj = i & 31;
        int chunk = jj >> 4, j = jj & 15;
        int gr = rowblk + row;
        float4 v = make_float4(0.f, 0.f, 0.f, 0.f);
        if (gr < M) v = *(const float4*)(A + (size_t)gr * 128 + chunk * 64 + j * 4);
        uint32_t base = chunk ? A1O : A0O;
        int k2a = 2 * j, k2b = 2 * j + 1;
        int oa = base + (k2a >> 3) * 512 + row * 8 + (k2a & 3) * 2 + ((k2a >> 2) & 1);
        int ob = base + (k2b >> 3) * 512 + row * 8 + (k2b & 3) * 2 + ((k2b >> 2) & 1);
        sm[oa] = pack_f16x2(v.y, v.x);
        sm[ob] = pack_f16x2(v.w, v.z);
    }

    // f16x2 accumulators: [gate][ma][na][half], half0 = row q, half1 = row q+8
    uint32_t C[3][2][4][2];
#pragma unroll
    for (int g = 0; g < 3; g++)
#pragma unroll
        for (int i = 0; i < 2; i++)
#pragma unroll
            for (int j = 0; j < 4; j++) { C[g][i][j][0] = 0u; C[g][i][j][1] = 0u; }

    // ================= phase 1 =================
#pragma unroll
    for (int chunk = 0; chunk < 2; chunk++) {
        if (chunk == 1) {
            // B buffer free (sync below); stream in chunk1
#pragma unroll
            for (int t = 0; t < 12; t++) {
                int i = tid + t * 256;
                int g = i >> 10, off4 = i & 1023;
                cp_async16(sbase + (BBO + g * 4096 + off4 * 4) * 4,
                           W + g * 8192 + 4096 + off4 * 4, 16);
            }
            asm volatile("cp.async.commit_group;" ::: "memory");
        }
        asm volatile("cp.async.wait_group 0;" ::: "memory");
        __syncthreads();
        const uint32_t* Ac = sm + (chunk ? A1O : A0O);
#pragma unroll
        for (int ks = 0; ks < 4; ks++) {
            uint32_t a[2][4];
#pragma unroll
            for (int ma = 0; ma < 2; ma++) {
                int m = wm * 32 + ma * 16 + q;
                uint2 lo = *(const uint2*)&Ac[ks * 512 + m * 8 + r * 2];
                uint2 hi = *(const uint2*)&Ac[ks * 512 + (m + 8) * 8 + r * 2];
                a[ma][0] = lo.x; a[ma][2] = lo.y;
                a[ma][1] = hi.x; a[ma][3] = hi.y;
            }
#pragma unroll
            for (int g = 0; g < 3; g++) {
                const uint32_t* bs = sm + BBO + g * 4096;
#pragma unroll
                for (int na = 0; na < 4; na++) {
                    int n = wn * 32 + na * 8 + q;
                    uint2 b = *(const uint2*)&bs[ks * 1024 + n * 8 + r * 2];
#pragma unroll
                    for (int ma = 0; ma < 2; ma++) mma_f16a(C[g][ma][na], a[ma], b.x, b.y);
                }
            }
        }
        __syncthreads();  // B reads done (after chunk1: A reads done too)
    }

    // ---- stream gcn_w (both chunks, 8192 u32 = 2048 f4) into B buffer ----
#pragma unroll
    for (int t = 0; t < 8; t++) {
        int i = tid + t * 256;
        cp_async16(sbase + (BBO + i * 4) * 4, W + 3 * 8192 + i * 4, 16);
    }
    asm volatile("cp.async.commit_group;" ::: "memory");

    // ============ LSTM epilogue -> Hs (f16x2 fragment-image) into A0/A1 =====
#pragma unroll
    for (int ma = 0; ma < 2; ma++) {
#pragma unroll
        for (int half = 0; half < 2; half++) {
            int lrow = wm * 32 + ma * 16 + q + half * 8;
#pragma unroll
            for (int na = 0; na < 4; na++) {
                int ch = wn * 32 + na * 8 + 2 * r;
                float2 zi2 = unpack_f16x2(C[0][ma][na][half]);
                float2 zc2 = unpack_f16x2(C[1][ma][na][half]);
                float2 zo2 = unpack_f16x2(C[2][ma][na][half]);
                float hlo, hhi;
                {
                    float zi = zi2.x + __ldg(g_cb0 + ch);
                    float zc = zc2.x + __ldg(g_cb1 + ch);
                    float zo = zo2.x + __ldg(g_cb2 + ch);
                    float I = sigfast(zi);
                    float T = tanhfast(zc);
                    float Cs = I * T;
                    float O = sigfast(zo + __ldg(g_wc2 + ch) * Cs);
                    hlo = O * tanhfast(Cs);
                }
                {
                    float zi = zi2.y + __ldg(g_cb0 + ch + 1);
                    float zc = zc2.y + __ldg(g_cb1 + ch + 1);
                    float zo = zo2.y + __ldg(g_cb2 + ch + 1);
                    float I = sigfast(zi);
                    float T = tanhfast(zc);
                    float Cs = I * T;
                    float O = sigfast(zo + __ldg(g_wc2 + ch + 1) * Cs);
                    hhi = O * tanhfast(Cs);
                }
                int k2 = ch >> 1;                 // 0..63
                int cchunk = k2 >> 5;
                int k2l = k2 & 31;
                int off = (cchunk ? A1O : A0O) + (k2l >> 3) * 512 + lrow * 8
                        + (k2l & 3) * 2 + ((k2l >> 2) & 1);
                sm[off] = pack_f16x2(hhi, hlo);
            }
        }
    }
    asm volatile("cp.async.wait_group 0;" ::: "memory");  // gcn_w ready
    __syncthreads();

    // ================= phase 2: hh = Hs @ gcn_w (f16 acc) ===================
    uint32_t D[2][4][2];
#pragma unroll
    for (int i = 0; i < 2; i++)
#pragma unroll
        for (int j = 0; j < 4; j++) { D[i][j][0] = 0u; D[i][j][1] = 0u; }

#pragma unroll
    for (int chunk = 0; chunk < 2; chunk++) {
        const uint32_t* as = sm + (chunk ? A1O : A0O);
        const uint32_t* bs = sm + BBO + chunk * 4096;
#pragma unroll
        for (int ks = 0; ks < 4; ks++) {
            uint32_t a[2][4];
#pragma unroll
            for (int ma = 0; ma < 2; ma++) {
                int m = wm * 32 + ma * 16 + q;
                uint2 lo = *(const uint2*)&as[ks * 512 + m * 8 + r * 2];
                uint2 hi = *(const uint2*)&as[ks * 512 + (m + 8) * 8 + r * 2];
                a[ma][0] = lo.x; a[ma][2] = lo.y;
                a[ma][1] = hi.x; a[ma][3] = hi.y;
            }
#pragma unroll
            for (int na = 0; na < 4; na++) {
                int n = wn * 32 + na * 8 + q;
                uint2 b = *(const uint2*)&bs[ks * 1024 + n * 8 + r * 2];
#pragma unroll
                for (int ma = 0; ma < 2; ma++) mma_f16a(D[ma][na], a[ma], b.x, b.y);
            }
        }
    }

    // ---- epilogue 2: write hh as bf16x2 ----
#pragma unroll
    for (int ma = 0; ma < 2; ma++) {
#pragma unroll
        for (int half = 0; half < 2; half++) {
            int row = rowblk + wm * 32 + ma * 16 + q + half * 8;
            if (row >= M) continue;
#pragma unroll
            for (int na = 0; na < 4; na++) {
                int ch = wn * 32 + na * 8 + 2 * r;
                float2 f = unpack_f16x2(D[ma][na][half]);
                out[(size_t)row * 64 + (ch >> 1)] = pack_bf16x2(f.y, f.x);
            }
        }
    }
}

// ============================================================================
// gather + finalize: warp per node, bf16 hh, unroll-by-8 for MLP
// ============================================================================
__global__ __launch_bounds__(256) void gather_finalize(const float* __restrict__ gcn_b,
                                                       float* __restrict__ out)
{
    int node = (blockIdx.x * blockDim.x + threadIdx.x) >> 5;
    int lane = threadIdx.x & 31;
    if (node >= N_NODES) return;
    int base = g_off[node];
    int cnt = g_off[node + 1] - base;
    float dgi = g_dg[node];

    const uint2* hh2 = (const uint2*)g_hhb;
    uint2 hv = hh2[(size_t)node * 32 + lane];
    float a0 = dgi * bf_lo(hv.x), a1 = dgi * bf_hi(hv.x);
    float a2 = dgi * bf_lo(hv.y), a3 = dgi * bf_hi(hv.y);

    for (int e0 = 0; e0 < cnt; e0 += 32) {
        int myidx = (e0 + lane < cnt) ? g_csr[base + e0 + lane] : 0;
        int lim = min(32, cnt - e0);
        int t = 0;
        for (; t + 8 <= lim; t += 8) {
            int s[8];
#pragma unroll
            for (int u = 0; u < 8; u++) s[u] = __shfl_sync(0xffffffffu, myidx, t + u);
            float d[8];
#pragma unroll
            for (int u = 0; u < 8; u++) d[u] = __ldg(g_dg + s[u]);
            uint2 v[8];
#pragma unroll
            for (int u = 0; u < 8; u++) v[u] = __ldg(hh2 + (size_t)s[u] * 32 + lane);
#pragma unroll
            for (int u = 0; u < 8; u++) {
                a0 = fmaf(d[u], bf_lo(v[u].x), a0);
                a1 = fmaf(d[u], bf_hi(v[u].x), a1);
                a2 = fmaf(d[u], bf_lo(v[u].y), a2);
                a3 = fmaf(d[u], bf_hi(v[u].y), a3);
            }
        }
        for (; t < lim; t++) {
            int s = __shfl_sync(0xffffffffu, myidx, t);
            float ds = __ldg(g_dg + s);
            uint2 v = __ldg(hh2 + (size_t)s * 32 + lane);
            a0 = fmaf(ds, bf_lo(v.x), a0);
            a1 = fmaf(ds, bf_hi(v.x), a1);
            a2 = fmaf(ds, bf_lo(v.y), a2);
            a3 = fmaf(ds, bf_hi(v.y), a3);
        }
    }

    float4 gb = ((const float4*)gcn_b)[lane];
    float4 fa = ((const float4*)g_fa)[lane];
    float sum = fmaxf(dgi * a0 + gb.x, 0.0f) * fa.x
              + fmaxf(dgi * a1 + gb.y, 0.0f) * fa.y
              + fmaxf(dgi * a2 + gb.z, 0.0f) * fa.z
              + fmaxf(dgi * a3 + gb.w, 0.0f) * fa.w;
#pragma unroll
    for (int o = 16; o > 0; o >>= 1) sum += __shfl_down_sync(0xffffffffu, sum, o);
    if (lane == 0) out[node] = sum + g_fc;
}

// ============================================================================
// launch. gemm_fused stays the 4th launched kernel for ncu capture.
// ============================================================================
extern "C" void kernel_launch(void* const* d_in, const int* in_sizes, int n_in,
                              void* d_out, int out_size)
{
    const float* x        = (const float*)d_in[0];
    const int*   ei       = (const int*)  d_in[1];
    const float* W_x      = (const float*)d_in[3];
    const float* w_c      = (const float*)d_in[4];
    const float* b        = (const float*)d_in[5];
    const float* theta_b  = (const float*)d_in[7];
    const float* gcn_w    = (const float*)d_in[8];
    const float* gcn_b    = (const float*)d_in[9];
    const float* bn_gamma = (const float*)d_in[10];
    const float* bn_beta  = (const float*)d_in[11];
    const float* bn_mean  = (const float*)d_in[12];
    const float* bn_var   = (const float*)d_in[13];
    const float* lin_w    = (const float*)d_in[14];
    const float* lin_b    = (const float*)d_in[15];
    float* out = (float*)d_out;

    const int* src = ei;
    const int* dst = ei + N_EDGES;

    const int SMF = SMU * 4;  // 65536 B

    static cudaStream_t s1 = nullptr;
    static cudaEvent_t evRoot, evCsr;
    if (!s1) {
        cudaStreamCreateWithFlags(&s1, cudaStreamNonBlocking);
        cudaEventCreateWithFlags(&evRoot, cudaEventDisableTiming);
        cudaEventCreateWithFlags(&evCsr,  cudaEventDisableTiming);
        cudaFuncSetAttribute((const void*)gemm_fused,
                             cudaFuncAttributeMaxDynamicSharedMemorySize, SMF);
    }

    uint32_t *hhp, *wcp;
    cudaGetSymbolAddress((void**)&hhp, g_hhb);
    cudaGetSymbolAddress((void**)&wcp, g_Wc);

    // fork s1 from main at graph root
    cudaEventRecord(evRoot, 0);
    cudaStreamWaitEvent(s1, evRoot, 0);

    prep_all<<<129, 256>>>(W_x, gcn_w, theta_b, b, w_c,                 // #1 (main)
                           bn_gamma, bn_beta, bn_mean, bn_var, lin_w, lin_b);
    count_kernel<<<(N_EDGES + 255) / 256, 256, 0, s1>>>(dst);           // #2 (s1)
    scan_a<<<NB, 256, 0, s1>>>();                                       // #3 (s1)
    gemm_fused<<<(N_NODES + 63) / 64, 256, SMF>>>(x, wcp, hhp, N_NODES); // #4 (main)
    scan_bc<<<NB, 256, 0, s1>>>();                                      // #5 (s1)
    fill_kernel<<<(N_EDGES + 255) / 256, 256, 0, s1>>>(src, dst);       // #6 (s1)
    cudaEventRecord(evCsr, s1);

    // join: gather needs gemm (stream order) + CSR (event)
    cudaStreamWaitEvent(0, evCsr, 0);
    gather_finalize<<<(N_NODES * 32 + 255) / 256, 256>>>(gcn_b, out);   // #7 (main)
}